// round 16
// baseline (speedup 1.0000x reference)
#include <cuda_runtime.h>
#include <cuda_fp16.h>
#include <cstdint>

// ============================================================================
// EdgeMLP: f = MLP(edges[:, :3]); out[i][j] = (cls1[i]==cls2[j]) * cos(f1[i],f2[j])
// Round 16: pair = R14 (pipelined A LDG, best 42.9us) with IT=16 to amortize
// prologue. feat = fused float4 W1 row (1 LDS.128 per k instead of 4 scalar).
// ============================================================================

#define N_MAX 8192
#define KK 32

__device__ __half g_h1[N_MAX * KK];   // A features, per-row u32-permuted
__device__ __half g_h2[N_MAX * KK];   // B features, natural layout
__device__ int    g_c1[N_MAX];
__device__ int    g_c2[N_MAX];

// ----------------------------------------------------------------------------
// Kernel 1: MLP + normalize, 4 threads per row (each 8 of 32 outputs).
// A-side rows are written u32-permuted: orig u32 j -> pos 4*(j%4) + j/4.
// ----------------------------------------------------------------------------
__global__ void __launch_bounds__(256) feat_kernel(
    const float* __restrict__ e1, const float* __restrict__ e2, int N1, int N2,
    const float* __restrict__ W1, const float* __restrict__ b1,
    const float* __restrict__ W2, const float* __restrict__ b2)
{
    __shared__ float4 sW14[64];           // (W1[0][k], W1[1][k], W1[2][k], b1[k])
    __shared__ float  sW2[2048], sb2[32];
    int t = threadIdx.x;
    if (t < 64) sW14[t] = make_float4(W1[t], W1[64 + t], W1[128 + t], b1[t]);
    for (int i = t; i < 2048; i += 256) sW2[i] = W2[i];
    if (t >= 64 && t < 96) sb2[t - 64] = b2[t - 64];
    __syncthreads();

    int gid  = blockIdx.x * 256 + t;
    int row2 = gid >> 2;
    int s    = gid & 3;
    if (row2 >= N1 + N2) return;

    bool isA = (row2 < N1);
    const float* ed = isA ? e1 : e2;
    int row = isA ? row2 : row2 - N1;

    float4 e = reinterpret_cast<const float4*>(ed)[row];

    float f[8];
    #pragma unroll
    for (int q = 0; q < 8; q++) f[q] = sb2[s * 8 + q];

    #pragma unroll 8
    for (int k = 0; k < 64; k++) {
        float4 wv = sW14[k];
        float h = fmaf(e.x, wv.x, fmaf(e.y, wv.y, fmaf(e.z, wv.z, wv.w)));
        h = fmaxf(h, 0.0f);
        const float4* w = reinterpret_cast<const float4*>(&sW2[k * 32 + s * 8]);
        float4 w0 = w[0], w1 = w[1];
        f[0] = fmaf(h, w0.x, f[0]); f[1] = fmaf(h, w0.y, f[1]);
        f[2] = fmaf(h, w0.z, f[2]); f[3] = fmaf(h, w0.w, f[3]);
        f[4] = fmaf(h, w1.x, f[4]); f[5] = fmaf(h, w1.y, f[5]);
        f[6] = fmaf(h, w1.z, f[6]); f[7] = fmaf(h, w1.w, f[7]);
    }

    float p = 0.0f;
    #pragma unroll
    for (int q = 0; q < 8; q++) p = fmaf(f[q], f[q], p);
    p += __shfl_xor_sync(0xFFFFFFFFu, p, 1);
    p += __shfl_xor_sync(0xFFFFFFFFu, p, 2);
    float inv = rsqrtf(fmaxf(p, 1e-24f));

    uint32_t o[4];
    #pragma unroll
    for (int q = 0; q < 4; q++) {
        __half2 h2 = __floats2half2_rn(f[2 * q] * inv, f[2 * q + 1] * inv);
        o[q] = *reinterpret_cast<uint32_t*>(&h2);
    }

    if (isA) {
        // this thread holds original u32s j = 4s + i; dest pos = 4i + s
        uint32_t* dst = reinterpret_cast<uint32_t*>(g_h1) + (size_t)row * 16;
        #pragma unroll
        for (int i = 0; i < 4; i++) dst[4 * i + s] = o[i];
        if (s == 0) g_c1[row] = (int)e.w;
    } else {
        *reinterpret_cast<uint4*>(g_h2 + (size_t)row * KK + s * 8) =
            *reinterpret_cast<uint4*>(o);
        if (s == 0) g_c2[row] = (int)e.w;
    }
}

// ----------------------------------------------------------------------------
__device__ __forceinline__ void hmma(float c[4], const uint32_t a[4], const uint32_t b[2]) {
    asm volatile(
        "mma.sync.aligned.m16n8k16.row.col.f32.f16.f16.f32 "
        "{%0,%1,%2,%3}, {%4,%5,%6,%7}, {%8,%9}, {%0,%1,%2,%3};"
        : "+f"(c[0]), "+f"(c[1]), "+f"(c[2]), "+f"(c[3])
        : "r"(a[0]), "r"(a[1]), "r"(a[2]), "r"(a[3]), "r"(b[0]), "r"(b[1]));
}

__device__ __forceinline__ void stg256(float* p, const float v[8]) {
    asm volatile(
        "st.global.v8.b32 [%0], {%1,%2,%3,%4,%5,%6,%7,%8};"
        :: "l"(p),
           "r"(__float_as_uint(v[0])), "r"(__float_as_uint(v[1])),
           "r"(__float_as_uint(v[2])), "r"(__float_as_uint(v[3])),
           "r"(__float_as_uint(v[4])), "r"(__float_as_uint(v[5])),
           "r"(__float_as_uint(v[6])), "r"(__float_as_uint(v[7]))
        : "memory");
}

__device__ __forceinline__ void cp_async16(uint32_t smem_dst, const void* gsrc) {
    asm volatile("cp.async.cg.shared.global [%0], [%1], 16;" :: "r"(smem_dst), "l"(gsrc));
}
#define CP_COMMIT() asm volatile("cp.async.commit_group;")
#define CP_WAIT0()  asm volatile("cp.async.wait_group 0;")

// B column permutation within each 32-col slab: thread q owns 8 contiguous
// global output columns, enabling masked STG.256.
__device__ __forceinline__ int bperm_row(int j) {
    int jl = j & 31;
    int r  = ((jl >> 1) & 3) * 8 + ((jl >> 3) & 3) * 2 + (jl & 1);
    return (j & ~31) + r;
}

// ----------------------------------------------------------------------------
// Kernel 2: strip of IT subtiles (32 rows x 128 cols) per CTA, barrier-free,
// software-pipelined A loads. 8 warps (2 M x 4 N), warp subtile 16x32.
// ----------------------------------------------------------------------------
#define RS 40   // smem row stride in halves (80B)
#define IT 16   // i-subtiles per CTA strip (512 rows) -> grid 1024

__global__ void __launch_bounds__(256, 3) pair_kernel(float* __restrict__ out, int N2)
{
    __shared__ __half Bs[128][RS];        // B tile (permuted), read once

    int t    = threadIdx.x;
    int wid  = t >> 5;
    int lane = t & 31;
    int j0   = blockIdx.x * 128;
    int i0   = blockIdx.y * (32 * IT);

    // --- Prologue: cp.async B (permuted) ---
    #pragma unroll
    for (int p = 0; p < 2; p++) {
        int v = t + p * 256;
        int row = v >> 2, c16 = v & 3;
        uint32_t dst = (uint32_t)__cvta_generic_to_shared(&Bs[bperm_row(row)][c16 * 8]);
        cp_async16(dst, (const char*)(g_h2 + (size_t)(j0 + row) * KK) + c16 * 16);
    }
    CP_COMMIT();

    int warp_m = wid >> 2;     // 0..1
    int warp_n = wid & 3;      // 0..3
    int r4 = lane >> 2;        // 0..7
    int q  = lane & 3;         // 0..3
    int c2 = q * 2;

    // Column-class LUT: bit (c*8 + v) set iff column v's class == c.
    int cb = warp_n * 32 + 8 * q;
    unsigned long long lut = 0ULL;
    #pragma unroll
    for (int v = 0; v < 8; v++) {
        int c = g_c2[j0 + cb + v] & 7;
        lut |= 1ULL << (c * 8 + v);
    }

    // Row classes for the whole strip, packed 4-bit (no in-loop LDGs).
    int rA = warp_m * 16 + r4;
    unsigned long long clsA = 0, clsB = 0;
    #pragma unroll
    for (int it = 0; it < IT; it++) {
        clsA |= (unsigned long long)(g_c1[i0 + it * 32 + rA]     & 7) << (4 * it);
        clsB |= (unsigned long long)(g_c1[i0 + it * 32 + rA + 8] & 7) << (4 * it);
    }

    CP_WAIT0();
    __syncthreads();           // the ONLY barrier

    // --- Hoist B fragments into registers (reused for all IT subtiles) ---
    uint32_t bf[2][4][2];
    #pragma unroll
    for (int k = 0; k < 2; k++) {
        int kc = c2 + k * 16;
        #pragma unroll
        for (int nt = 0; nt < 4; nt++) {
            int col = warp_n * 32 + nt * 8 + r4;
            bf[k][nt][0] = *reinterpret_cast<const uint32_t*>(&Bs[col][kc    ]);
            bf[k][nt][1] = *reinterpret_cast<const uint32_t*>(&Bs[col][kc + 8]);
        }
    }

    const uint4* aBase = reinterpret_cast<const uint4*>(g_h1)
                       + (size_t)(i0 + rA) * 4 + q;        // 4 uint4 per row
    float* rowPtrA = out + (size_t)(i0 + rA)     * (size_t)N2 + (size_t)(j0 + cb);
    float* rowPtrB = out + (size_t)(i0 + rA + 8) * (size_t)N2 + (size_t)(j0 + cb);
    size_t stepOut = (size_t)32 * (size_t)N2;

    // --- Software pipeline: A for subtile 0 in flight before the loop ---
    uint4 A0 = __ldg(aBase);            // row rA
    uint4 A1 = __ldg(aBase + 8 * 4);    // row rA + 8

    #pragma unroll
    for (int it = 0; it < IT; it++) {
        // Prefetch A(it+1) before consuming A(it)
        uint4 A0n, A1n;
        if (it < IT - 1) {
            const uint4* nb = aBase + (size_t)(it + 1) * 32 * 4;
            A0n = __ldg(nb);
            A1n = __ldg(nb + 8 * 4);
        }

        float acc[4][4];
        #pragma unroll
        for (int nt = 0; nt < 4; nt++)
            #pragma unroll
            for (int v = 0; v < 4; v++) acc[nt][v] = 0.0f;

        {   // k = 0: af = {(rA,kc),(rA+8,kc),(rA,kc+8),(rA+8,kc+8)}
            uint32_t af[4] = { A0.x, A1.x, A0.y, A1.y };
            #pragma unroll
            for (int nt = 0; nt < 4; nt++)
                hmma(acc[nt], af, bf[0][nt]);
        }
        {   // k = 1
            uint32_t af[4] = { A0.z, A1.z, A0.w, A1.w };
            #pragma unroll
            for (int nt = 0; nt < 4; nt++)
                hmma(acc[nt], af, bf[1][nt]);
        }

        // Row classes from packed registers (ALU only)
        unsigned mA = (unsigned)(lut >> (((unsigned)(clsA >> (4 * it)) & 7u) * 8)) & 0xFFu;
        unsigned mB = (unsigned)(lut >> (((unsigned)(clsB >> (4 * it)) & 7u) * 8)) & 0xFFu;

        float va[8], vb[8];
        #pragma unroll
        for (int nt = 0; nt < 4; nt++) {
            va[2 * nt]     = (mA & (1u << (2 * nt)))     ? acc[nt][0] : 0.0f;
            va[2 * nt + 1] = (mA & (1u << (2 * nt + 1))) ? acc[nt][1] : 0.0f;
            vb[2 * nt]     = (mB & (1u << (2 * nt)))     ? acc[nt][2] : 0.0f;
            vb[2 * nt + 1] = (mB & (1u << (2 * nt + 1))) ? acc[nt][3] : 0.0f;
        }
        stg256(rowPtrA, va);
        stg256(rowPtrB, vb);
        rowPtrA += stepOut;
        rowPtrB += stepOut;

        A0 = A0n;
        A1 = A1n;
    }
}

// ----------------------------------------------------------------------------
extern "C" void kernel_launch(void* const* d_in, const int* in_sizes, int n_in,
                              void* d_out, int out_size)
{
    const float* edges1 = (const float*)d_in[0];
    const float* edges2 = (const float*)d_in[1];
    const float* W1     = (const float*)d_in[2];
    const float* b1     = (const float*)d_in[3];
    const float* W2     = (const float*)d_in[4];
    const float* b2     = (const float*)d_in[5];
    float* out = (float*)d_out;

    int N1 = in_sizes[0] / 4;
    int N2 = in_sizes[1] / 4;

    int totalThreads = (N1 + N2) * 4;
    feat_kernel<<<(totalThreads + 255) / 256, 256>>>(edges1, edges2, N1, N2, W1, b1, W2, b2);

    dim3 grid(N2 / 128, N1 / (32 * IT));
    pair_kernel<<<grid, 256>>>(out, N2);
}

// round 17
// speedup vs baseline: 1.2845x; 1.2845x over previous
#include <cuda_runtime.h>
#include <cuda_fp16.h>
#include <cstdint>

// ============================================================================
// EdgeMLP: f = MLP(edges[:, :3]); out[i][j] = (cls1[i]==cls2[j]) * cos(f1[i],f2[j])
// Round 17: pair reverted to R14 exactly (IT=8, grid 2048, pipelined A LDG --
// best measured 42.9us). feat keeps the fused float4 W1 row (1 LDS.128/k).
// ============================================================================

#define N_MAX 8192
#define KK 32

__device__ __half g_h1[N_MAX * KK];   // A features, per-row u32-permuted
__device__ __half g_h2[N_MAX * KK];   // B features, natural layout
__device__ int    g_c1[N_MAX];
__device__ int    g_c2[N_MAX];

// ----------------------------------------------------------------------------
// Kernel 1: MLP + normalize, 4 threads per row (each 8 of 32 outputs).
// A-side rows are written u32-permuted: orig u32 j -> pos 4*(j%4) + j/4.
// ----------------------------------------------------------------------------
__global__ void __launch_bounds__(256) feat_kernel(
    const float* __restrict__ e1, const float* __restrict__ e2, int N1, int N2,
    const float* __restrict__ W1, const float* __restrict__ b1,
    const float* __restrict__ W2, const float* __restrict__ b2)
{
    __shared__ float4 sW14[64];           // (W1[0][k], W1[1][k], W1[2][k], b1[k])
    __shared__ float  sW2[2048], sb2[32];
    int t = threadIdx.x;
    if (t < 64) sW14[t] = make_float4(W1[t], W1[64 + t], W1[128 + t], b1[t]);
    for (int i = t; i < 2048; i += 256) sW2[i] = W2[i];
    if (t >= 64 && t < 96) sb2[t - 64] = b2[t - 64];
    __syncthreads();

    int gid  = blockIdx.x * 256 + t;
    int row2 = gid >> 2;
    int s    = gid & 3;
    if (row2 >= N1 + N2) return;

    bool isA = (row2 < N1);
    const float* ed = isA ? e1 : e2;
    int row = isA ? row2 : row2 - N1;

    float4 e = reinterpret_cast<const float4*>(ed)[row];

    float f[8];
    #pragma unroll
    for (int q = 0; q < 8; q++) f[q] = sb2[s * 8 + q];

    #pragma unroll 8
    for (int k = 0; k < 64; k++) {
        float4 wv = sW14[k];
        float h = fmaf(e.x, wv.x, fmaf(e.y, wv.y, fmaf(e.z, wv.z, wv.w)));
        h = fmaxf(h, 0.0f);
        const float4* w = reinterpret_cast<const float4*>(&sW2[k * 32 + s * 8]);
        float4 w0 = w[0], w1 = w[1];
        f[0] = fmaf(h, w0.x, f[0]); f[1] = fmaf(h, w0.y, f[1]);
        f[2] = fmaf(h, w0.z, f[2]); f[3] = fmaf(h, w0.w, f[3]);
        f[4] = fmaf(h, w1.x, f[4]); f[5] = fmaf(h, w1.y, f[5]);
        f[6] = fmaf(h, w1.z, f[6]); f[7] = fmaf(h, w1.w, f[7]);
    }

    float p = 0.0f;
    #pragma unroll
    for (int q = 0; q < 8; q++) p = fmaf(f[q], f[q], p);
    p += __shfl_xor_sync(0xFFFFFFFFu, p, 1);
    p += __shfl_xor_sync(0xFFFFFFFFu, p, 2);
    float inv = rsqrtf(fmaxf(p, 1e-24f));

    uint32_t o[4];
    #pragma unroll
    for (int q = 0; q < 4; q++) {
        __half2 h2 = __floats2half2_rn(f[2 * q] * inv, f[2 * q + 1] * inv);
        o[q] = *reinterpret_cast<uint32_t*>(&h2);
    }

    if (isA) {
        // this thread holds original u32s j = 4s + i; dest pos = 4i + s
        uint32_t* dst = reinterpret_cast<uint32_t*>(g_h1) + (size_t)row * 16;
        #pragma unroll
        for (int i = 0; i < 4; i++) dst[4 * i + s] = o[i];
        if (s == 0) g_c1[row] = (int)e.w;
    } else {
        *reinterpret_cast<uint4*>(g_h2 + (size_t)row * KK + s * 8) =
            *reinterpret_cast<uint4*>(o);
        if (s == 0) g_c2[row] = (int)e.w;
    }
}

// ----------------------------------------------------------------------------
__device__ __forceinline__ void hmma(float c[4], const uint32_t a[4], const uint32_t b[2]) {
    asm volatile(
        "mma.sync.aligned.m16n8k16.row.col.f32.f16.f16.f32 "
        "{%0,%1,%2,%3}, {%4,%5,%6,%7}, {%8,%9}, {%0,%1,%2,%3};"
        : "+f"(c[0]), "+f"(c[1]), "+f"(c[2]), "+f"(c[3])
        : "r"(a[0]), "r"(a[1]), "r"(a[2]), "r"(a[3]), "r"(b[0]), "r"(b[1]));
}

__device__ __forceinline__ void stg256(float* p, const float v[8]) {
    asm volatile(
        "st.global.v8.b32 [%0], {%1,%2,%3,%4,%5,%6,%7,%8};"
        :: "l"(p),
           "r"(__float_as_uint(v[0])), "r"(__float_as_uint(v[1])),
           "r"(__float_as_uint(v[2])), "r"(__float_as_uint(v[3])),
           "r"(__float_as_uint(v[4])), "r"(__float_as_uint(v[5])),
           "r"(__float_as_uint(v[6])), "r"(__float_as_uint(v[7]))
        : "memory");
}

__device__ __forceinline__ void cp_async16(uint32_t smem_dst, const void* gsrc) {
    asm volatile("cp.async.cg.shared.global [%0], [%1], 16;" :: "r"(smem_dst), "l"(gsrc));
}
#define CP_COMMIT() asm volatile("cp.async.commit_group;")
#define CP_WAIT0()  asm volatile("cp.async.wait_group 0;")

// B column permutation within each 32-col slab: thread q owns 8 contiguous
// global output columns, enabling masked STG.256.
__device__ __forceinline__ int bperm_row(int j) {
    int jl = j & 31;
    int r  = ((jl >> 1) & 3) * 8 + ((jl >> 3) & 3) * 2 + (jl & 1);
    return (j & ~31) + r;
}

// ----------------------------------------------------------------------------
// Kernel 2: strip of IT subtiles (32 rows x 128 cols) per CTA, barrier-free,
// software-pipelined A loads. 8 warps (2 M x 4 N), warp subtile 16x32.
// ----------------------------------------------------------------------------
#define RS 40   // smem row stride in halves (80B)
#define IT 8    // i-subtiles per CTA strip (256 rows) -> grid 2048, ~4.6 waves

__global__ void __launch_bounds__(256, 3) pair_kernel(float* __restrict__ out, int N2)
{
    __shared__ __half Bs[128][RS];        // B tile (permuted), read once

    int t    = threadIdx.x;
    int wid  = t >> 5;
    int lane = t & 31;
    int j0   = blockIdx.x * 128;
    int i0   = blockIdx.y * (32 * IT);

    // --- Prologue: cp.async B (permuted) ---
    #pragma unroll
    for (int p = 0; p < 2; p++) {
        int v = t + p * 256;
        int row = v >> 2, c16 = v & 3;
        uint32_t dst = (uint32_t)__cvta_generic_to_shared(&Bs[bperm_row(row)][c16 * 8]);
        cp_async16(dst, (const char*)(g_h2 + (size_t)(j0 + row) * KK) + c16 * 16);
    }
    CP_COMMIT();

    int warp_m = wid >> 2;     // 0..1
    int warp_n = wid & 3;      // 0..3
    int r4 = lane >> 2;        // 0..7
    int q  = lane & 3;         // 0..3
    int c2 = q * 2;

    // Column-class LUT: bit (c*8 + v) set iff column v's class == c.
    int cb = warp_n * 32 + 8 * q;
    unsigned long long lut = 0ULL;
    #pragma unroll
    for (int v = 0; v < 8; v++) {
        int c = g_c2[j0 + cb + v] & 7;
        lut |= 1ULL << (c * 8 + v);
    }

    // Row classes for the whole strip, packed 4-bit (no in-loop LDGs).
    int rA = warp_m * 16 + r4;
    unsigned clsA = 0, clsB = 0;
    #pragma unroll
    for (int it = 0; it < IT; it++) {
        clsA |= (unsigned)(g_c1[i0 + it * 32 + rA]     & 7) << (4 * it);
        clsB |= (unsigned)(g_c1[i0 + it * 32 + rA + 8] & 7) << (4 * it);
    }

    CP_WAIT0();
    __syncthreads();           // the ONLY barrier

    // --- Hoist B fragments into registers (reused for all IT subtiles) ---
    uint32_t bf[2][4][2];
    #pragma unroll
    for (int k = 0; k < 2; k++) {
        int kc = c2 + k * 16;
        #pragma unroll
        for (int nt = 0; nt < 4; nt++) {
            int col = warp_n * 32 + nt * 8 + r4;
            bf[k][nt][0] = *reinterpret_cast<const uint32_t*>(&Bs[col][kc    ]);
            bf[k][nt][1] = *reinterpret_cast<const uint32_t*>(&Bs[col][kc + 8]);
        }
    }

    const uint4* aBase = reinterpret_cast<const uint4*>(g_h1)
                       + (size_t)(i0 + rA) * 4 + q;        // 4 uint4 per row
    float* rowPtrA = out + (size_t)(i0 + rA)     * (size_t)N2 + (size_t)(j0 + cb);
    float* rowPtrB = out + (size_t)(i0 + rA + 8) * (size_t)N2 + (size_t)(j0 + cb);
    size_t stepOut = (size_t)32 * (size_t)N2;

    // --- Software pipeline: A for subtile 0 in flight before the loop ---
    uint4 A0 = __ldg(aBase);            // row rA
    uint4 A1 = __ldg(aBase + 8 * 4);    // row rA + 8

    #pragma unroll
    for (int it = 0; it < IT; it++) {
        // Prefetch A(it+1) before consuming A(it)
        uint4 A0n, A1n;
        if (it < IT - 1) {
            const uint4* nb = aBase + (size_t)(it + 1) * 32 * 4;
            A0n = __ldg(nb);
            A1n = __ldg(nb + 8 * 4);
        }

        float acc[4][4];
        #pragma unroll
        for (int nt = 0; nt < 4; nt++)
            #pragma unroll
            for (int v = 0; v < 4; v++) acc[nt][v] = 0.0f;

        {   // k = 0: af = {(rA,kc),(rA+8,kc),(rA,kc+8),(rA+8,kc+8)}
            uint32_t af[4] = { A0.x, A1.x, A0.y, A1.y };
            #pragma unroll
            for (int nt = 0; nt < 4; nt++)
                hmma(acc[nt], af, bf[0][nt]);
        }
        {   // k = 1
            uint32_t af[4] = { A0.z, A1.z, A0.w, A1.w };
            #pragma unroll
            for (int nt = 0; nt < 4; nt++)
                hmma(acc[nt], af, bf[1][nt]);
        }

        // Row classes from packed registers (ALU only)
        unsigned mA = (unsigned)(lut >> (((clsA >> (4 * it)) & 7u) * 8)) & 0xFFu;
        unsigned mB = (unsigned)(lut >> (((clsB >> (4 * it)) & 7u) * 8)) & 0xFFu;

        float va[8], vb[8];
        #pragma unroll
        for (int nt = 0; nt < 4; nt++) {
            va[2 * nt]     = (mA & (1u << (2 * nt)))     ? acc[nt][0] : 0.0f;
            va[2 * nt + 1] = (mA & (1u << (2 * nt + 1))) ? acc[nt][1] : 0.0f;
            vb[2 * nt]     = (mB & (1u << (2 * nt)))     ? acc[nt][2] : 0.0f;
            vb[2 * nt + 1] = (mB & (1u << (2 * nt + 1))) ? acc[nt][3] : 0.0f;
        }
        stg256(rowPtrA, va);
        stg256(rowPtrB, vb);
        rowPtrA += stepOut;
        rowPtrB += stepOut;

        A0 = A0n;
        A1 = A1n;
    }
}

// ----------------------------------------------------------------------------
extern "C" void kernel_launch(void* const* d_in, const int* in_sizes, int n_in,
                              void* d_out, int out_size)
{
    const float* edges1 = (const float*)d_in[0];
    const float* edges2 = (const float*)d_in[1];
    const float* W1     = (const float*)d_in[2];
    const float* b1     = (const float*)d_in[3];
    const float* W2     = (const float*)d_in[4];
    const float* b2     = (const float*)d_in[5];
    float* out = (float*)d_out;

    int N1 = in_sizes[0] / 4;
    int N2 = in_sizes[1] / 4;

    int totalThreads = (N1 + N2) * 4;
    feat_kernel<<<(totalThreads + 255) / 256, 256>>>(edges1, edges2, N1, N2, W1, b1, W2, b2);

    dim3 grid(N2 / 128, N1 / (32 * IT));
    pair_kernel<<<grid, 256>>>(out, N2);
}